// round 5
// baseline (speedup 1.0000x reference)
#include <cuda_runtime.h>
#include <math.h>

// Problem constants
#define U 64
#define M 8192
#define D 64
#define SCHUNKS 64                      // k_scores chunks (128 slots each)
#define CHUNKS 16                       // k_weighted chunks
#define SLOTS_PER_CHUNK (M / CHUNKS)    // 512

// Output layout (float32, tuple concatenated):
//   outputs  [64,64]      at 0
//   weights  [64,8192]    at 4096
//   memories [64,8192,64] at 528384
#define OFF_OUTPUTS  0
#define OFF_WEIGHTS  (U * D)
#define OFF_MEMCOPY  (U * D + U * M)

// Scratch (device globals; no allocation)
__device__ float2 g_stats[U * SCHUNKS];          // per-(unit,chunk) (max, sumexp)
__device__ float  g_partial[U * CHUNKS * D];     // per-(unit,chunk) partial outputs
__device__ int    g_cnt[U];                      // arrival counters (self-resetting)

// ---------------------------------------------------------------------------
// Kernel 1: raw scores + online-softmax chunk stats.
// Grid (64 chunks, 64 units), 256 threads = 8 warps x 16 slots.
// Lanes split 16+16: each half covers one 64-float row via float4 (LDG.128).
// ---------------------------------------------------------------------------
__global__ void k_scores(const float* __restrict__ att,
                         const float* __restrict__ atts,
                         const int*   __restrict__ mask,
                         const float* __restrict__ tmpr,
                         float*       __restrict__ w_out)
{
    __shared__ float2 sred[16];

    int u    = blockIdx.y;
    int warp = threadIdx.x >> 5;          // 0..7
    int lane = threadIdx.x & 31;
    int idx  = lane & 15;                 // float4 lane within row
    int half = lane >> 4;                 // row parity within step
    int slot0 = blockIdx.x * 128 + warp * 16;

    float4 q4    = ((const float4*)(att + (u << 6)))[idx];
    float  inv_t = 1.0f / tmpr[u];
    const float4* base = (const float4*)(atts + ((size_t)u << 19));
    float*       wrow = w_out + ((size_t)u << 13);
    const int*   mrow = mask  + ((size_t)u << 13);

    float v[8];
    #pragma unroll
    for (int i = 0; i < 8; i++) {
        int m = slot0 + 2 * i + half;
        float4 r = __ldcs(&base[(size_t)m * 16 + idx]);
        float s = r.x * q4.x + r.y * q4.y + r.z * q4.z + r.w * q4.w;
        s += __shfl_xor_sync(0xffffffffu, s, 8);
        s += __shfl_xor_sync(0xffffffffu, s, 4);
        s += __shfl_xor_sync(0xffffffffu, s, 2);
        s += __shfl_xor_sync(0xffffffffu, s, 1);
        if (idx == 0) {
            if (__ldg(&mrow[m])) s = -1e9f;   // RandomMask before temperature
            s *= inv_t;
            v[i] = s;
            __stcg(&wrow[m], s);              // raw score, keep L2-resident
        }
    }

    // Per-participant (lanes 0 and 16 of each warp) local max + sumexp over 8
    if (idx == 0) {
        float mx = v[0];
        #pragma unroll
        for (int i = 1; i < 8; i++) mx = fmaxf(mx, v[i]);
        float se = 0.f;
        #pragma unroll
        for (int i = 0; i < 8; i++) se += __expf(v[i] - mx);
        sred[warp * 2 + half] = make_float2(mx, se);
    }
    __syncthreads();

    // Warp 0, lanes 0..15: combine 16 partials -> chunk (max, sumexp)
    if (threadIdx.x < 16) {
        float2 p = sred[threadIdx.x];
        float mx = p.x;
        #pragma unroll
        for (int o = 8; o > 0; o >>= 1)
            mx = fmaxf(mx, __shfl_xor_sync(0xffffu, mx, o));
        float se = p.y * __expf(p.x - mx);
        #pragma unroll
        for (int o = 8; o > 0; o >>= 1)
            se += __shfl_xor_sync(0xffffu, se, o);
        if (threadIdx.x == 0)
            g_stats[u * SCHUNKS + blockIdx.x] = make_float2(mx, se);
    }
}

// ---------------------------------------------------------------------------
// Kernel 2: combine stats -> normalize scores -> weights out; fused memories
// copy + weighted sum; last-block-per-unit final reduction -> outputs.
// Grid (16 chunks of 512 slots, 64 units), 256 threads = 16 rows x 16 lanes.
// ---------------------------------------------------------------------------
__global__ void k_weighted(const float* __restrict__ mem,
                           float*       __restrict__ w,        // raw in, norm out
                           float*       __restrict__ mem_copy,
                           float*       __restrict__ outputs)
{
    __shared__ float  ws[SLOTS_PER_CHUNK];
    __shared__ float4 red[16][16];
    __shared__ float2 stat;                      // (max_u, inv_sum_u)
    __shared__ int    is_last;

    int u     = blockIdx.y;
    int chunk = blockIdx.x;
    int m0    = chunk * SLOTS_PER_CHUNK;
    int tid   = threadIdx.x;

    // Warp 0: combine the 64 chunk stats (fixed order -> identical in all blocks)
    if (tid < 32) {
        const float2* st = &g_stats[u * SCHUNKS];
        float2 a = st[tid];
        float2 b = st[tid + 32];
        float mx = fmaxf(a.x, b.x);
        #pragma unroll
        for (int o = 16; o > 0; o >>= 1)
            mx = fmaxf(mx, __shfl_xor_sync(0xffffffffu, mx, o));
        float se = a.y * __expf(a.x - mx) + b.y * __expf(b.x - mx);
        #pragma unroll
        for (int o = 16; o > 0; o >>= 1)
            se += __shfl_xor_sync(0xffffffffu, se, o);
        if (tid == 0) stat = make_float2(mx, 1.0f / se);
    }
    __syncthreads();
    float mx      = stat.x;
    float inv_sum = stat.y;

    // Normalize raw scores -> shared + weights output (2 per thread)
    float* wrow = w + ((size_t)u << 13) + m0;
    {
        float w0 = __expf(wrow[tid]       - mx) * inv_sum;
        float w1 = __expf(wrow[tid + 256] - mx) * inv_sum;
        ws[tid]       = w0;
        ws[tid + 256] = w1;
        wrow[tid]       = w0;
        wrow[tid + 256] = w1;
    }
    __syncthreads();

    int lane = tid & 15;
    int r    = tid >> 4;

    size_t base = ((size_t)u << 19) + ((size_t)m0 << 6);
    const float4* src = (const float4*)(mem + base);
    float4*       dst = (float4*)(mem_copy + base);

    float4 acc = make_float4(0.f, 0.f, 0.f, 0.f);
    #pragma unroll 8
    for (int i = 0; i < SLOTS_PER_CHUNK / 16; i++) {   // 32 iterations
        int m = r + i * 16;
        float4 vv = __ldcs(&src[(size_t)m * 16 + lane]);
        __stcs(&dst[(size_t)m * 16 + lane], vv);
        float wm = ws[m];
        acc.x = fmaf(wm, vv.x, acc.x);
        acc.y = fmaf(wm, vv.y, acc.y);
        acc.z = fmaf(wm, vv.z, acc.z);
        acc.w = fmaf(wm, vv.w, acc.w);
    }

    red[r][lane] = acc;
    __syncthreads();
    if (r == 0) {
        float4 s = red[0][lane];
        #pragma unroll
        for (int j = 1; j < 16; j++) {
            s.x += red[j][lane].x;
            s.y += red[j][lane].y;
            s.z += red[j][lane].z;
            s.w += red[j][lane].w;
        }
        ((float4*)g_partial)[((size_t)u * CHUNKS + chunk) * 16 + lane] = s;
    }

    // Make this block's partial visible, then arrive on the unit counter.
    __threadfence();
    __syncthreads();
    if (tid == 0)
        is_last = (atomicAdd(&g_cnt[u], 1) == CHUNKS - 1) ? 1 : 0;
    __syncthreads();

    // Last block for this unit performs the deterministic 16-chunk reduction
    if (is_last) {
        __threadfence();
        if (tid < 16) {
            const float4* p = (const float4*)g_partial + (size_t)u * CHUNKS * 16;
            float4 s = make_float4(0.f, 0.f, 0.f, 0.f);
            #pragma unroll
            for (int c = 0; c < CHUNKS; c++) {
                float4 q = p[c * 16 + tid];
                s.x += q.x; s.y += q.y; s.z += q.z; s.w += q.w;
            }
            ((float4*)outputs)[u * 16 + tid] = s;
        }
        if (tid == 0) g_cnt[u] = 0;     // self-reset for next graph replay
    }
}

// ---------------------------------------------------------------------------
extern "C" void kernel_launch(void* const* d_in, const int* in_sizes, int n_in,
                              void* d_out, int out_size)
{
    const float* att  = (const float*)d_in[0];   // [64,64]
    const float* atts = (const float*)d_in[1];   // [64,8192,64]
    const float* mem  = (const float*)d_in[2];   // [64,8192,64]
    const float* tmpr = (const float*)d_in[3];   // [64,1]
    const int*   mask = (const int*)  d_in[4];   // [64,8192] bool->int32

    float* out      = (float*)d_out;
    float* outputs  = out + OFF_OUTPUTS;
    float* weights  = out + OFF_WEIGHTS;
    float* mem_copy = out + OFF_MEMCOPY;

    // 1) raw scores + softmax chunk stats
    {
        dim3 grid(SCHUNKS, U);
        k_scores<<<grid, 256>>>(att, atts, mask, tmpr, weights);
    }
    // 2) normalize + fused copy/weighted-sum + final reduce
    {
        dim3 grid(CHUNKS, U);
        k_weighted<<<grid, 256>>>(mem, weights, mem_copy, outputs);
    }
}

// round 6
// speedup vs baseline: 1.1475x; 1.1475x over previous
#include <cuda_runtime.h>
#include <math.h>

// Problem constants
#define U 64
#define M 8192
#define D 64
#define SCHUNKS 64                      // k_scores chunks (128 slots each)
#define CHUNKS 16                       // k_weighted chunks
#define SLOTS_PER_CHUNK (M / CHUNKS)    // 512

// k_weighted TMA pipeline
#define STAGE_SLOTS 32
#define STAGE_BYTES (STAGE_SLOTS * D * 4)          // 8192
#define NSTAGES 4
#define NITERS (SLOTS_PER_CHUNK / STAGE_SLOTS)     // 16

// Output layout (float32, tuple concatenated):
//   outputs  [64,64]      at 0
//   weights  [64,8192]    at 4096
//   memories [64,8192,64] at 528384
#define OFF_OUTPUTS  0
#define OFF_WEIGHTS  (U * D)
#define OFF_MEMCOPY  (U * D + U * M)

// Scratch (device globals; no allocation)
__device__ float2 g_stats[U * SCHUNKS];          // per-(unit,chunk) (max, sumexp)
__device__ float  g_partial[U * CHUNKS * D];     // per-(unit,chunk) partial outputs
__device__ int    g_cnt[U];                      // arrival counters (self-resetting)

// ---------------------------------------------------------------------------
// mbarrier / bulk-async helpers
// ---------------------------------------------------------------------------
__device__ __forceinline__ unsigned smem_u32(const void* p) {
    return (unsigned)__cvta_generic_to_shared(p);
}
__device__ __forceinline__ void mbar_init(unsigned a, unsigned cnt) {
    asm volatile("mbarrier.init.shared.b64 [%0], %1;" :: "r"(a), "r"(cnt) : "memory");
}
__device__ __forceinline__ void mbar_expect_tx(unsigned a, unsigned bytes) {
    asm volatile("mbarrier.arrive.expect_tx.shared.b64 _, [%0], %1;"
                 :: "r"(a), "r"(bytes) : "memory");
}
__device__ __forceinline__ void mbar_wait(unsigned a, unsigned parity) {
    asm volatile(
        "{\n\t.reg .pred p;\n\t"
        "WL_%=:\n\t"
        "mbarrier.try_wait.parity.acquire.cta.shared::cta.b64 p, [%0], %1, 0x989680;\n\t"
        "@!p bra WL_%=;\n\t}"
        :: "r"(a), "r"(parity) : "memory");
}
__device__ __forceinline__ void bulk_load(unsigned dst_smem, const void* src,
                                          unsigned bytes, unsigned mbar) {
    asm volatile(
        "cp.async.bulk.shared::cluster.global.mbarrier::complete_tx::bytes "
        "[%0], [%1], %2, [%3];"
        :: "r"(dst_smem), "l"(src), "r"(bytes), "r"(mbar) : "memory");
}

// ---------------------------------------------------------------------------
// Kernel 1: raw scores + online-softmax chunk stats (unchanged from R4).
// Grid (64 chunks, 64 units), 256 threads = 8 warps x 16 slots.
// ---------------------------------------------------------------------------
__global__ void k_scores(const float* __restrict__ att,
                         const float* __restrict__ atts,
                         const int*   __restrict__ mask,
                         const float* __restrict__ tmpr,
                         float*       __restrict__ w_out)
{
    __shared__ float2 sred[16];

    int u    = blockIdx.y;
    int warp = threadIdx.x >> 5;
    int lane = threadIdx.x & 31;
    int idx  = lane & 15;
    int half = lane >> 4;
    int slot0 = blockIdx.x * 128 + warp * 16;

    float4 q4    = ((const float4*)(att + (u << 6)))[idx];
    float  inv_t = 1.0f / tmpr[u];
    const float4* base = (const float4*)(atts + ((size_t)u << 19));
    float*       wrow = w_out + ((size_t)u << 13);
    const int*   mrow = mask  + ((size_t)u << 13);

    float v[8];
    #pragma unroll
    for (int i = 0; i < 8; i++) {
        int m = slot0 + 2 * i + half;
        float4 r = __ldcs(&base[(size_t)m * 16 + idx]);
        float s = r.x * q4.x + r.y * q4.y + r.z * q4.z + r.w * q4.w;
        s += __shfl_xor_sync(0xffffffffu, s, 8);
        s += __shfl_xor_sync(0xffffffffu, s, 4);
        s += __shfl_xor_sync(0xffffffffu, s, 2);
        s += __shfl_xor_sync(0xffffffffu, s, 1);
        if (idx == 0) {
            if (__ldg(&mrow[m])) s = -1e9f;   // RandomMask before temperature
            s *= inv_t;
            v[i] = s;
            __stcg(&wrow[m], s);              // raw score, keep L2-resident
        }
    }

    if (idx == 0) {
        float mx = v[0];
        #pragma unroll
        for (int i = 1; i < 8; i++) mx = fmaxf(mx, v[i]);
        float se = 0.f;
        #pragma unroll
        for (int i = 0; i < 8; i++) se += __expf(v[i] - mx);
        sred[warp * 2 + half] = make_float2(mx, se);
    }
    __syncthreads();

    if (threadIdx.x < 16) {
        float2 p = sred[threadIdx.x];
        float mx = p.x;
        #pragma unroll
        for (int o = 8; o > 0; o >>= 1)
            mx = fmaxf(mx, __shfl_xor_sync(0xffffu, mx, o));
        float se = p.y * __expf(p.x - mx);
        #pragma unroll
        for (int o = 8; o > 0; o >>= 1)
            se += __shfl_xor_sync(0xffffu, se, o);
        if (threadIdx.x == 0)
            g_stats[u * SCHUNKS + blockIdx.x] = make_float2(mx, se);
    }
}

// ---------------------------------------------------------------------------
// Kernel 2: combine stats -> normalize -> weights; TMA-staged memories
// (cp.async.bulk -> smem pipeline); fused copy (STG from smem data) +
// weighted sum; last-block-per-unit reduction -> outputs.
// Grid (16 chunks of 512 slots, 64 units), 256 threads = 16 rows x 16 lanes.
// ---------------------------------------------------------------------------
__global__ void __launch_bounds__(256)
k_weighted(const float* __restrict__ mem,
           float*       __restrict__ w,        // raw in, norm out
           float*       __restrict__ mem_copy,
           float*       __restrict__ outputs)
{
    __shared__ __align__(128) float4 stage[NSTAGES][STAGE_SLOTS * 16]; // 32 KB
    __shared__ float  ws[SLOTS_PER_CHUNK];                             // 2 KB
    __shared__ float4 red[16][16];                                     // 4 KB
    __shared__ __align__(8) unsigned long long mbar[NSTAGES];
    __shared__ float2 stat;
    __shared__ int    is_last;

    int u     = blockIdx.y;
    int chunk = blockIdx.x;
    int m0    = chunk * SLOTS_PER_CHUNK;
    int tid   = threadIdx.x;

    // Warp 0: combine the 64 chunk stats (fixed order -> identical in all blocks)
    if (tid < 32) {
        const float2* st = &g_stats[u * SCHUNKS];
        float2 a = st[tid];
        float2 b = st[tid + 32];
        float mx = fmaxf(a.x, b.x);
        #pragma unroll
        for (int o = 16; o > 0; o >>= 1)
            mx = fmaxf(mx, __shfl_xor_sync(0xffffffffu, mx, o));
        float se = a.y * __expf(a.x - mx) + b.y * __expf(b.x - mx);
        #pragma unroll
        for (int o = 16; o > 0; o >>= 1)
            se += __shfl_xor_sync(0xffffffffu, se, o);
        if (tid == 0) stat = make_float2(mx, 1.0f / se);
    }
    // mbarrier init + TMA prologue issued by thread 0 after stats combine
    if (tid == 0) {
        #pragma unroll
        for (int i = 0; i < NSTAGES; i++) mbar_init(smem_u32(&mbar[i]), 1);
    }
    __syncthreads();

    float mx      = stat.x;
    float inv_sum = stat.y;

    size_t base = ((size_t)u << 19) + ((size_t)m0 << 6);   // floats
    const char* gsrc = (const char*)(mem + base);

    if (tid == 0) {
        #pragma unroll
        for (int p = 0; p < NSTAGES; p++) {
            unsigned mb = smem_u32(&mbar[p]);
            mbar_expect_tx(mb, STAGE_BYTES);
            bulk_load(smem_u32(&stage[p][0]), gsrc + (size_t)p * STAGE_BYTES,
                      STAGE_BYTES, mb);
        }
    }

    // Normalize raw scores -> shared + weights output (overlaps with TMA)
    float* wrow = w + ((size_t)u << 13) + m0;
    {
        float w0 = __expf(wrow[tid]       - mx) * inv_sum;
        float w1 = __expf(wrow[tid + 256] - mx) * inv_sum;
        ws[tid]       = w0;
        ws[tid + 256] = w1;
        wrow[tid]       = w0;
        wrow[tid + 256] = w1;
    }
    __syncthreads();

    int lane = tid & 15;
    int r    = tid >> 4;
    float4* dst = (float4*)(mem_copy + base);

    float4 acc = make_float4(0.f, 0.f, 0.f, 0.f);
    for (int s = 0; s < NITERS; s++) {
        int buf = s & (NSTAGES - 1);
        mbar_wait(smem_u32(&mbar[buf]), (s >> 2) & 1);

        int mloc = s * STAGE_SLOTS;
        float4 v0 = stage[buf][r * 16 + lane];
        float4 v1 = stage[buf][(r + 16) * 16 + lane];
        __stcs(&dst[(size_t)(mloc + r) * 16 + lane], v0);
        __stcs(&dst[(size_t)(mloc + r + 16) * 16 + lane], v1);
        float w0 = ws[mloc + r];
        float w1 = ws[mloc + r + 16];
        acc.x = fmaf(w0, v0.x, fmaf(w1, v1.x, acc.x));
        acc.y = fmaf(w0, v0.y, fmaf(w1, v1.y, acc.y));
        acc.z = fmaf(w0, v0.z, fmaf(w1, v1.z, acc.z));
        acc.w = fmaf(w0, v0.w, fmaf(w1, v1.w, acc.w));

        __syncthreads();        // all consumers done with buf
        if (tid == 0 && s + NSTAGES < NITERS) {
            unsigned mb = smem_u32(&mbar[buf]);
            mbar_expect_tx(mb, STAGE_BYTES);
            bulk_load(smem_u32(&stage[buf][0]),
                      gsrc + (size_t)(s + NSTAGES) * STAGE_BYTES,
                      STAGE_BYTES, mb);
        }
    }

    red[r][lane] = acc;
    __syncthreads();
    if (r == 0) {
        float4 s = red[0][lane];
        #pragma unroll
        for (int j = 1; j < 16; j++) {
            s.x += red[j][lane].x;
            s.y += red[j][lane].y;
            s.z += red[j][lane].z;
            s.w += red[j][lane].w;
        }
        ((float4*)g_partial)[((size_t)u * CHUNKS + chunk) * 16 + lane] = s;
    }

    // Make this block's partial visible, then arrive on the unit counter.
    __threadfence();
    __syncthreads();
    if (tid == 0)
        is_last = (atomicAdd(&g_cnt[u], 1) == CHUNKS - 1) ? 1 : 0;
    __syncthreads();

    if (is_last) {
        __threadfence();
        if (tid < 16) {
            const float4* p = (const float4*)g_partial + (size_t)u * CHUNKS * 16;
            float4 s = make_float4(0.f, 0.f, 0.f, 0.f);
            #pragma unroll
            for (int c = 0; c < CHUNKS; c++) {
                float4 q = p[c * 16 + tid];
                s.x += q.x; s.y += q.y; s.z += q.z; s.w += q.w;
            }
            ((float4*)outputs)[u * 16 + tid] = s;
        }
        if (tid == 0) g_cnt[u] = 0;     // self-reset for next graph replay
    }
}

// ---------------------------------------------------------------------------
extern "C" void kernel_launch(void* const* d_in, const int* in_sizes, int n_in,
                              void* d_out, int out_size)
{
    const float* att  = (const float*)d_in[0];   // [64,64]
    const float* atts = (const float*)d_in[1];   // [64,8192,64]
    const float* mem  = (const float*)d_in[2];   // [64,8192,64]
    const float* tmpr = (const float*)d_in[3];   // [64,1]
    const int*   mask = (const int*)  d_in[4];   // [64,8192] bool->int32

    float* out      = (float*)d_out;
    float* outputs  = out + OFF_OUTPUTS;
    float* weights  = out + OFF_WEIGHTS;
    float* mem_copy = out + OFF_MEMCOPY;

    // 1) raw scores + softmax chunk stats
    {
        dim3 grid(SCHUNKS, U);
        k_scores<<<grid, 256>>>(att, atts, mask, tmpr, weights);
    }
    // 2) normalize + TMA-staged copy/weighted-sum + final reduce
    {
        dim3 grid(CHUNKS, U);
        k_weighted<<<grid, 256>>>(mem, weights, mem_copy, outputs);
    }
}